// round 7
// baseline (speedup 1.0000x reference)
#include <cuda_runtime.h>
#include <cuda_bf16.h>

// DigitCaps fused single-kernel for GB300 (sm_103a), round 7.
//
//   output[b,c] = (sum_n u[b,n,:]) . dc_new[c,:] / N
//   dc_new      = dc + (seg_u - counts*dc) / (B*N)
// One streaming pass computes sum_u[128][8], seg_u[10][8], counts[10] in global
// scratch; the LAST block (atomic counter) finalizes and re-zeroes the scratch.
//
// Round-7: latency-chain surgery. Integer-key IMNMX argmax (replaces 13-cyc
// FSETP chain), f32x2 sims (dc in 40 f32x2 regs; fits the 170-reg cap at 192
// threads x 2 blocks), packed-register counts, unroll-2 item loop.

#define Bsz    128
#define Jtot   4608
#define Cc     10
#define Dd     8
#define Mm     4
#define Ntot   (Jtot * Mm)          // 18432

#define JB     24
#define BB     32
#define NTHR   192
#define WSTR   260                  // padded W row stride (floats), 16B-aligned rows
#define XSTR   196                  // padded X row stride (floats), 16B-aligned rows
#define NSEG   40                   // 40 bf16x2 seg slots (counts live in registers)
#define NBLK   ((Jtot / JB) * (Bsz / BB))   // 192 * 4 = 768

// scratch: [0,1024) sum_u[b][d]; [1024,1104) seg[c*8+d]; [1104,1114) cnt[c]
__device__ float    g_scratch[1120];
__device__ unsigned g_done;

// ---- packed f32x2 helpers ----
__device__ __forceinline__ unsigned long long pk2(float lo, float hi) {
    unsigned long long r;
    asm("mov.b64 %0, {%1, %2};" : "=l"(r) : "f"(lo), "f"(hi));
    return r;
}
__device__ __forceinline__ float2 upk2(unsigned long long a) {
    float2 r;
    asm("mov.b64 {%0, %1}, %2;" : "=f"(r.x), "=f"(r.y) : "l"(a));
    return r;
}
__device__ __forceinline__ unsigned long long fma2(unsigned long long a,
                                                   unsigned long long b,
                                                   unsigned long long c) {
    unsigned long long d;
    asm("fma.rn.f32x2 %0, %1, %2, %3;" : "=l"(d) : "l"(a), "l"(b), "l"(c));
    return d;
}
__device__ __forceinline__ unsigned long long mul2(unsigned long long a,
                                                   unsigned long long b) {
    unsigned long long d;
    asm("mul.rn.f32x2 %0, %1, %2;" : "=l"(d) : "l"(a), "l"(b));
    return d;
}
__device__ __forceinline__ unsigned long long add2(unsigned long long a,
                                                   unsigned long long b) {
    unsigned long long d;
    asm("add.rn.f32x2 %0, %1, %2;" : "=l"(d) : "l"(a), "l"(b));
    return d;
}
// (lo,hi) f32 pair -> bf16x2 (lo in bits[15:0])
__device__ __forceinline__ unsigned cvt_bf16x2(unsigned long long p) {
    float2 t = upk2(p);
    unsigned r;
    asm("cvt.rn.bf16x2.f32 %0, %1, %2;" : "=r"(r) : "f"(t.y), "f"(t.x));
    return r;
}
__device__ __forceinline__ __nv_bfloat162 as_bf2(unsigned v) {
    return *(__nv_bfloat162*)&v;
}
// monotone unsigned key for f32 ordering: pos -> bits|0x80000000, neg -> ~bits
__device__ __forceinline__ unsigned fkey(float f) {
    unsigned b = __float_as_uint(f);
    unsigned m = ((int)b >> 31) | 0x80000000u;   // SHF + (fused) OR
    return b ^ m;                                 // one LOP3 total for ^(|)
}

extern __shared__ float smem[];

__global__ __launch_bounds__(NTHR, 2)
void caps_main_kernel(const float* __restrict__ xin,   // [B, J, 8]
                      const float* __restrict__ Wg,    // [J, 8, 32]
                      const float* __restrict__ dcg,   // [10, 8]
                      float* __restrict__ out)         // [128*10 + 80]
{
    float*    sW   = smem;                               // JB*WSTR = 6240 f
    float*    sX   = sW + JB * WSTR;                     // BB*XSTR = 6272 f
    unsigned* sSeg = (unsigned*)(sX + BB * XSTR);        // NSEG*NTHR = 7680 u32

    const int tid = threadIdx.x;
    const int j0  = blockIdx.x * JB;
    const int b0  = blockIdx.y * BB;

    // ---- stage W tile: 24 rows x 64 float4 ----
    {
        const float4* src = (const float4*)(Wg + (size_t)j0 * 256);
        #pragma unroll 4
        for (int i = tid; i < JB * 64; i += NTHR) {
            int jl = i >> 6, r = i & 63;
            ((float4*)(sW + jl * WSTR))[r] = src[i];
        }
    }
    // ---- stage X tile: 32 rows x 48 float4 ----
    {
        for (int i = tid; i < BB * 48; i += NTHR) {
            int bl = i / 48, r = i - bl * 48;
            const float4* src =
                (const float4*)(xin + (size_t)(b0 + bl) * (Jtot * 8) + (size_t)j0 * 8);
            ((float4*)(sX + bl * XSTR))[r] = src[r];
        }
    }
    // ---- zero private seg columns (uint4) ----
    {
        uint4 z = {0u, 0u, 0u, 0u};
        uint4* p = (uint4*)sSeg;
        #pragma unroll
        for (int i = tid; i < NSEG * NTHR / 4; i += NTHR) p[i] = z;
    }

    // ---- digit_caps as 40 f32x2 register pairs ----
    unsigned long long rdc[Cc * 4];
    #pragma unroll
    for (int i = 0; i < Cc * 4; i++) {
        float2 v = ((const float2*)dcg)[i];
        rdc[i] = pk2(v.x, v.y);
    }

    __syncthreads();

    const int bl  = tid / 6;        // fixed batch row per thread (0..31)
    const int sub = tid - bl * 6;   // 0..5

    unsigned long long su0 = 0, su1 = 0, su2 = 0, su3 = 0;
    unsigned long long cnt = 0;     // 10 x 6-bit packed counts (max 16 each)
    const float* xrow = sX + bl * XSTR;

    #pragma unroll 2
    for (int it = 0; it < 16; ++it) {
        const int p  = it * 6 + sub;   // 0..95
        const int jl = p >> 2;
        const int m  = p & 3;

        const float2*     xs   = (const float2*)(xrow + jl * 8);
        const ulonglong2* wrow = (const ulonglong2*)(sW + jl * WSTR);

        unsigned long long u0 = 0, u1 = 0, u2 = 0, u3 = 0;
        #pragma unroll
        for (int k = 0; k < 4; k++) {
            float2 xp = xs[k];
            unsigned long long xa = pk2(xp.x, xp.x);
            unsigned long long xb = pk2(xp.y, xp.y);
            ulonglong2 wA = wrow[(2 * k) * 8 + m * 2];
            ulonglong2 wB = wrow[(2 * k) * 8 + m * 2 + 1];
            u0 = fma2(xa, wA.x, u0);
            u1 = fma2(xa, wA.y, u1);
            u2 = fma2(xa, wB.x, u2);
            u3 = fma2(xa, wB.y, u3);
            ulonglong2 wC = wrow[(2 * k + 1) * 8 + m * 2];
            ulonglong2 wD = wrow[(2 * k + 1) * 8 + m * 2 + 1];
            u0 = fma2(xb, wC.x, u0);
            u1 = fma2(xb, wC.y, u1);
            u2 = fma2(xb, wD.x, u2);
            u3 = fma2(xb, wD.y, u3);
        }

        su0 = add2(su0, u0); su1 = add2(su1, u1);
        su2 = add2(su2, u2); su3 = add2(su3, u3);

        // argmax via monotone integer keys + IMNMX chain (first-max semantics:
        // low 4 bits carry (15-c), so equal sims resolve to the smaller c).
        unsigned best = 0;
        #pragma unroll
        for (int c = 0; c < Cc; c++) {
            unsigned long long acc = mul2(u0, rdc[4 * c]);
            acc = fma2(u1, rdc[4 * c + 1], acc);
            acc = fma2(u2, rdc[4 * c + 2], acc);
            acc = fma2(u3, rdc[4 * c + 3], acc);
            float2 t = upk2(acc);
            unsigned key = (fkey(t.x + t.y) & 0xFFFFFFF0u) | (unsigned)(15 - c);
            best = (key > best) ? key : best;    // IMNMX.U32
        }
        const int wbest = 15 - (int)(best & 0xFu);

        // bf16 votes for segment accumulation (off the argmax path)
        unsigned v0 = cvt_bf16x2(u0), v1 = cvt_bf16x2(u1);
        unsigned v2 = cvt_bf16x2(u2), v3 = cvt_bf16x2(u3);

        // per-thread-private bf16x2 seg columns (bank = tid%32, conflict-free)
        unsigned* segp = sSeg + wbest * (4 * NTHR) + tid;
        {
            unsigned o;
            __nv_bfloat162 r;
            o = segp[0 * NTHR]; r = __hadd2(as_bf2(o), as_bf2(v0)); segp[0 * NTHR] = *(unsigned*)&r;
            o = segp[1 * NTHR]; r = __hadd2(as_bf2(o), as_bf2(v1)); segp[1 * NTHR] = *(unsigned*)&r;
            o = segp[2 * NTHR]; r = __hadd2(as_bf2(o), as_bf2(v2)); segp[2 * NTHR] = *(unsigned*)&r;
            o = segp[3 * NTHR]; r = __hadd2(as_bf2(o), as_bf2(v3)); segp[3 * NTHR] = *(unsigned*)&r;
        }
        cnt += 1ull << (6 * wbest);
    }

    __syncthreads();   // everyone done with tiles + seg columns

    // ---- stage counts (10 slots) and su (8 slots) into the sW region ----
    #pragma unroll
    for (int c = 0; c < Cc; c++)
        sW[c * NTHR + tid] = (float)((cnt >> (6 * c)) & 63ull);
    {
        float2 t;
        t = upk2(su0); sW[(10 + 0) * NTHR + tid] = t.x; sW[(10 + 1) * NTHR + tid] = t.y;
        t = upk2(su1); sW[(10 + 2) * NTHR + tid] = t.x; sW[(10 + 3) * NTHR + tid] = t.y;
        t = upk2(su2); sW[(10 + 4) * NTHR + tid] = t.x; sW[(10 + 5) * NTHR + tid] = t.y;
        t = upk2(su3); sW[(10 + 6) * NTHR + tid] = t.x; sW[(10 + 7) * NTHR + tid] = t.y;
    }
    __syncthreads();

    // ---- block reduction: 6 warps over 58 slots ----
    const int warp = tid >> 5;
    const int lane = tid & 31;
    for (int slot = warp; slot < 58; slot += 6) {
        if (slot < 40) {
            // bf16x2 seg column -> f32 pair
            const unsigned* base = sSeg + slot * NTHR;
            float sx = 0.0f, sy = 0.0f;
            #pragma unroll
            for (int k = 0; k < 6; k++) {
                unsigned v = base[k * 32 + lane];
                float2 f = __bfloat1622float2(as_bf2(v));
                sx += f.x; sy += f.y;
            }
            #pragma unroll
            for (int d = 16; d > 0; d >>= 1) {
                sx += __shfl_xor_sync(0xffffffffu, sx, d);
                sy += __shfl_xor_sync(0xffffffffu, sy, d);
            }
            if (lane == 0) {
                int c = slot >> 2, dp = slot & 3;
                atomicAdd(&g_scratch[1024 + c * 8 + 2 * dp], sx);
                atomicAdd(&g_scratch[1024 + c * 8 + 2 * dp + 1], sy);
            }
        } else if (slot < 50) {
            // counts
            const float* base = sW + (slot - 40) * NTHR;
            float s = 0.0f;
            #pragma unroll
            for (int k = 0; k < 6; k++) s += base[k * 32 + lane];
            #pragma unroll
            for (int d = 16; d > 0; d >>= 1)
                s += __shfl_xor_sync(0xffffffffu, s, d);
            if (lane == 0) atomicAdd(&g_scratch[1104 + (slot - 40)], s);
        } else {
            // su: lane = local b, sum its 6 threads
            int d = slot - 50;
            const float* base = sW + (10 + d) * NTHR + lane * 6;
            float s = base[0] + base[1] + base[2] + base[3] + base[4] + base[5];
            atomicAdd(&g_scratch[(b0 + lane) * 8 + d], s);
        }
    }

    // ---- last-block finalize ----
    __threadfence();
    __syncthreads();
    __shared__ int sLast;
    if (tid == 0) {
        unsigned prev = atomicAdd(&g_done, 1u);
        sLast = (prev == NBLK - 1u);
    }
    __syncthreads();
    if (!sLast) return;

    __threadfence();   // acquire: all blocks' scratch writes visible

    float* s_sum = sW;          // 1024 floats
    float* dcn   = sW + 1024;   // 80 floats
    volatile float* gs = g_scratch;

    for (int i = tid; i < Bsz * Dd; i += NTHR) s_sum[i] = gs[i];
    if (tid < Cc * Dd) {
        int   c   = tid >> 3;
        float v   = dcg[tid];
        float upd = (gs[1024 + tid] - gs[1104 + c] * v)
                    * (1.0f / (float)(Bsz * Ntot));
        float nv  = v + upd;
        dcn[tid] = nv;
        out[Bsz * Cc + tid] = nv;          // digit_caps_new tail
    }
    __syncthreads();

    // self-clean scratch + counter for the next graph replay
    for (int i = tid; i < 1120; i += NTHR) g_scratch[i] = 0.0f;
    if (tid == 0) g_done = 0u;

    for (int idx = tid; idx < Bsz * Cc; idx += NTHR) {
        int bb = idx / Cc;
        int c  = idx - bb * Cc;
        float s = 0.0f;
        #pragma unroll
        for (int d = 0; d < Dd; d++) s += s_sum[bb * 8 + d] * dcn[c * 8 + d];
        out[idx] = s * (1.0f / (float)Ntot);
    }
}

extern "C" void kernel_launch(void* const* d_in, const int* in_sizes, int n_in,
                              void* d_out, int out_size)
{
    const float* xin = (const float*)d_in[0];  // inputs [128,12,12,32,8]
    const float* Wg  = (const float*)d_in[1];  // W [4608,8,32]
    const float* dcg = (const float*)d_in[2];  // digit_caps [10,8]
    float* out = (float*)d_out;

    size_t smemBytes = (size_t)(JB * WSTR + BB * XSTR + NSEG * NTHR) * sizeof(float);
    cudaFuncSetAttribute(caps_main_kernel,
                         cudaFuncAttributeMaxDynamicSharedMemorySize,
                         (int)smemBytes);
    dim3 grid(Jtot / JB, Bsz / BB);
    caps_main_kernel<<<grid, NTHR, smemBytes>>>(xin, Wg, dcg, out);
}

// round 11
// speedup vs baseline: 1.8072x; 1.8072x over previous
#include <cuda_runtime.h>
#include <cuda_bf16.h>

// DigitCaps fused single-kernel for GB300 (sm_103a), round 8 (re-bench after
// infra failure — identical candidate).
// = round-3 proven base (51.7us) + IMNMX argmax + fused last-block finalize
//   + register-packed counts. No other deltas.
//
//   output[b,c] = (sum_n u[b,n,:]) . dc_new[c,:] / N
//   dc_new      = dc + (seg_u - counts*dc) / (B*N)

#define Bsz    128
#define Jtot   4608
#define Cc     10
#define Dd     8
#define Mm     4
#define Ntot   (Jtot * Mm)          // 18432

#define JB     32
#define BB     32
#define NTHR   256
#define WSTR   260                  // padded W row stride (floats)
#define XSTR   258                  // padded X row stride (floats)
#define NSEG   40                   // 40 bf16x2 seg slots (counts in registers)
#define NBLK   ((Jtot / JB) * (Bsz / BB))   // 576

// scratch: [0,1024) sum_u[b][d]; [1024,1104) seg[c*8+d]; [1104,1114) cnt[c]
__device__ float    g_scratch[1120];
__device__ unsigned g_done;

// ---- packed f32x2 helpers ----
__device__ __forceinline__ unsigned long long pk2(float lo, float hi) {
    unsigned long long r;
    asm("mov.b64 %0, {%1, %2};" : "=l"(r) : "f"(lo), "f"(hi));
    return r;
}
__device__ __forceinline__ float2 upk2(unsigned long long a) {
    float2 r;
    asm("mov.b64 {%0, %1}, %2;" : "=f"(r.x), "=f"(r.y) : "l"(a));
    return r;
}
__device__ __forceinline__ unsigned long long fma2(unsigned long long a,
                                                   unsigned long long b,
                                                   unsigned long long c) {
    unsigned long long d;
    asm("fma.rn.f32x2 %0, %1, %2, %3;" : "=l"(d) : "l"(a), "l"(b), "l"(c));
    return d;
}
__device__ __forceinline__ unsigned long long mul2(unsigned long long a,
                                                   unsigned long long b) {
    unsigned long long d;
    asm("mul.rn.f32x2 %0, %1, %2;" : "=l"(d) : "l"(a), "l"(b));
    return d;
}
__device__ __forceinline__ unsigned long long add2(unsigned long long a,
                                                   unsigned long long b) {
    unsigned long long d;
    asm("add.rn.f32x2 %0, %1, %2;" : "=l"(d) : "l"(a), "l"(b));
    return d;
}
// (lo,hi) f32 pair -> bf16x2 (lo in bits[15:0])
__device__ __forceinline__ unsigned cvt_bf16x2(unsigned long long p) {
    float2 t = upk2(p);
    unsigned r;
    asm("cvt.rn.bf16x2.f32 %0, %1, %2;" : "=r"(r) : "f"(t.y), "f"(t.x));
    return r;
}
__device__ __forceinline__ __nv_bfloat162 as_bf2(unsigned v) {
    return *(__nv_bfloat162*)&v;
}
// monotone unsigned key for f32 ordering
__device__ __forceinline__ unsigned fkey(float f) {
    unsigned b = __float_as_uint(f);
    unsigned m = ((int)b >> 31) | 0x80000000u;
    return b ^ m;
}

extern __shared__ float smem[];

__global__ __launch_bounds__(NTHR, 2)
void caps_main_kernel(const float* __restrict__ xin,   // [B, J, 8]
                      const float* __restrict__ Wg,    // [J, 8, 32]
                      const float* __restrict__ dcg,   // [10, 8]
                      float* __restrict__ out)         // [128*10 + 80]
{
    float*    sW   = smem;                               // JB*WSTR = 8320 f
    float*    sX   = sW + JB * WSTR;                     // BB*XSTR = 8256 f
    unsigned* sSeg = (unsigned*)(sX + BB * XSTR);        // NSEG*256 u32

    const int tid = threadIdx.x;
    const int j0  = blockIdx.x * JB;
    const int b0  = blockIdx.y * BB;

    // ---- stage W tile (padded rows, float4) ----
    {
        const float4* src = (const float4*)(Wg + (size_t)j0 * 256);
        #pragma unroll 4
        for (int i = tid; i < JB * 64; i += NTHR) {
            int jl = i >> 6, r = i & 63;
            ((float4*)sW)[jl * (WSTR / 4) + r] = src[i];
        }
    }
    // ---- stage X tile (padded rows, float2) ----
    {
        for (int i = tid; i < BB * 128; i += NTHR) {
            int bl = i >> 7, r = i & 127;
            const float2* src =
                (const float2*)(xin + (size_t)(b0 + bl) * (Jtot * 8) + (size_t)j0 * 8);
            ((float2*)sX)[bl * (XSTR / 2) + r] = src[r];
        }
    }
    // ---- zero private seg columns ----
    for (int i = tid; i < NSEG * 256; i += NTHR) sSeg[i] = 0u;

    // ---- digit_caps as 40 f32x2 pairs in registers ----
    unsigned long long rdc[Cc * 4];
    #pragma unroll
    for (int i = 0; i < Cc * 4; i++) {
        float2 v = ((const float2*)dcg)[i];
        rdc[i] = pk2(v.x, v.y);
    }

    __syncthreads();

    const int bl  = tid >> 3;
    const int sub = tid & 7;
    const int b   = b0 + bl;

    unsigned long long su0 = 0, su1 = 0, su2 = 0, su3 = 0;
    unsigned long long cnt = 0;     // 10 x 6-bit packed counts (max 16/thread)
    const float2* xrow = (const float2*)sX + bl * (XSTR / 2);

    for (int it = 0; it < 16; ++it) {
        const int p  = it * 8 + sub;
        const int jl = p >> 2;
        const int m  = p & 3;

        const float2* xs = xrow + jl * 4;
        const float4* w4 = (const float4*)sW + jl * (WSTR / 4) + m * 2;

        unsigned long long u0 = 0, u1 = 0, u2 = 0, u3 = 0;
        #pragma unroll
        for (int k = 0; k < 4; k++) {
            float2 xp = xs[k];
            unsigned long long xa = pk2(xp.x, xp.x);
            unsigned long long xb = pk2(xp.y, xp.y);
            float4 wA = w4[(2 * k) * 8];
            float4 wB = w4[(2 * k) * 8 + 1];
            u0 = fma2(xa, pk2(wA.x, wA.y), u0);
            u1 = fma2(xa, pk2(wA.z, wA.w), u1);
            u2 = fma2(xa, pk2(wB.x, wB.y), u2);
            u3 = fma2(xa, pk2(wB.z, wB.w), u3);
            float4 wC = w4[(2 * k + 1) * 8];
            float4 wD = w4[(2 * k + 1) * 8 + 1];
            u0 = fma2(xb, pk2(wC.x, wC.y), u0);
            u1 = fma2(xb, pk2(wC.z, wC.w), u1);
            u2 = fma2(xb, pk2(wD.x, wD.y), u2);
            u3 = fma2(xb, pk2(wD.z, wD.w), u3);
        }

        su0 = add2(su0, u0); su1 = add2(su1, u1);
        su2 = add2(su2, u2); su3 = add2(su3, u3);

        // argmax via monotone integer keys + IMNMX chain (first-max semantics:
        // low 4 bits carry (15-c); near-ties resolve to the smaller c).
        unsigned best = 0;
        #pragma unroll
        for (int c = 0; c < Cc; c++) {
            unsigned long long acc = mul2(u0, rdc[4 * c]);
            acc = fma2(u1, rdc[4 * c + 1], acc);
            acc = fma2(u2, rdc[4 * c + 2], acc);
            acc = fma2(u3, rdc[4 * c + 3], acc);
            float2 t = upk2(acc);
            unsigned key = (fkey(t.x + t.y) & 0xFFFFFFF0u) | (unsigned)(15 - c);
            best = (key > best) ? key : best;    // IMNMX.U32
        }
        const int wbest = 15 - (int)(best & 0xFu);

        // bf16 votes for segment accumulation (off the argmax path)
        unsigned v0 = cvt_bf16x2(u0), v1 = cvt_bf16x2(u1);
        unsigned v2 = cvt_bf16x2(u2), v3 = cvt_bf16x2(u3);

        // per-thread-private bf16x2 seg columns (bank = tid%32, conflict-free)
        unsigned* segp = sSeg + wbest * 4 * 256 + tid;
        {
            unsigned o;
            __nv_bfloat162 r;
            o = segp[0];   r = __hadd2(as_bf2(o), as_bf2(v0)); segp[0]   = *(unsigned*)&r;
            o = segp[256]; r = __hadd2(as_bf2(o), as_bf2(v1)); segp[256] = *(unsigned*)&r;
            o = segp[512]; r = __hadd2(as_bf2(o), as_bf2(v2)); segp[512] = *(unsigned*)&r;
            o = segp[768]; r = __hadd2(as_bf2(o), as_bf2(v3)); segp[768] = *(unsigned*)&r;
        }
        cnt += 1ull << (6 * wbest);
    }

    // ---- sum_u: reduce over the 8 threads sharing b ----
    #pragma unroll
    for (int d = 1; d < 8; d <<= 1) {
        su0 = add2(su0, __shfl_xor_sync(0xffffffffu, su0, d));
        su1 = add2(su1, __shfl_xor_sync(0xffffffffu, su1, d));
        su2 = add2(su2, __shfl_xor_sync(0xffffffffu, su2, d));
        su3 = add2(su3, __shfl_xor_sync(0xffffffffu, su3, d));
    }
    if (sub == 0) {
        float2 t;
        t = upk2(su0); atomicAdd(&g_scratch[b * 8 + 0], t.x); atomicAdd(&g_scratch[b * 8 + 1], t.y);
        t = upk2(su1); atomicAdd(&g_scratch[b * 8 + 2], t.x); atomicAdd(&g_scratch[b * 8 + 3], t.y);
        t = upk2(su2); atomicAdd(&g_scratch[b * 8 + 4], t.x); atomicAdd(&g_scratch[b * 8 + 5], t.y);
        t = upk2(su3); atomicAdd(&g_scratch[b * 8 + 6], t.x); atomicAdd(&g_scratch[b * 8 + 7], t.y);
    }

    __syncthreads();   // tiles + seg columns complete

    // ---- stage packed counts into the (now free) sW region ----
    #pragma unroll
    for (int c = 0; c < Cc; c++)
        sW[c * NTHR + tid] = (float)((cnt >> (6 * c)) & 63ull);
    __syncthreads();

    // ---- block reduction: 8 warps over 50 slots (40 seg + 10 counts) ----
    const int warp = tid >> 5;
    const int lane = tid & 31;
    for (int slot = warp; slot < 50; slot += 8) {
        if (slot < 40) {
            const unsigned* base = sSeg + slot * 256;
            float sx = 0.0f, sy = 0.0f;
            #pragma unroll
            for (int k = 0; k < 8; k++) {
                unsigned v = base[k * 32 + lane];
                float2 f = __bfloat1622float2(as_bf2(v));
                sx += f.x; sy += f.y;
            }
            #pragma unroll
            for (int d = 16; d > 0; d >>= 1) {
                sx += __shfl_xor_sync(0xffffffffu, sx, d);
                sy += __shfl_xor_sync(0xffffffffu, sy, d);
            }
            if (lane == 0) {
                int c = slot >> 2, dp = slot & 3;
                atomicAdd(&g_scratch[1024 + c * 8 + 2 * dp], sx);
                atomicAdd(&g_scratch[1024 + c * 8 + 2 * dp + 1], sy);
            }
        } else {
            const float* base = sW + (slot - 40) * NTHR;
            float s = 0.0f;
            #pragma unroll
            for (int k = 0; k < 8; k++) s += base[k * 32 + lane];
            #pragma unroll
            for (int d = 16; d > 0; d >>= 1)
                s += __shfl_xor_sync(0xffffffffu, s, d);
            if (lane == 0) atomicAdd(&g_scratch[1104 + (slot - 40)], s);
        }
    }

    // ---- last-block finalize ----
    __threadfence();
    __syncthreads();
    __shared__ int sLast;
    if (tid == 0) {
        unsigned prev = atomicAdd(&g_done, 1u);
        sLast = (prev == NBLK - 1u);
    }
    __syncthreads();
    if (!sLast) return;

    __threadfence();   // acquire: all blocks' scratch writes visible

    float* s_sum = sW;          // 1024 floats (sW region reused)
    float* dcn   = sW + 1024;   // 80 floats
    volatile float* gs = g_scratch;

    for (int i = tid; i < Bsz * Dd; i += NTHR) s_sum[i] = gs[i];
    if (tid < Cc * Dd) {
        int   c   = tid >> 3;
        float v   = dcg[tid];
        float upd = (gs[1024 + tid] - gs[1104 + c] * v)
                    * (1.0f / (float)(Bsz * Ntot));
        float nv  = v + upd;
        dcn[tid] = nv;
        out[Bsz * Cc + tid] = nv;          // digit_caps_new tail
    }
    __syncthreads();

    // self-clean scratch + counter for the next graph replay
    for (int i = tid; i < 1120; i += NTHR) g_scratch[i] = 0.0f;
    if (tid == 0) g_done = 0u;

    for (int idx = tid; idx < Bsz * Cc; idx += NTHR) {
        int bb = idx / Cc;
        int c  = idx - bb * Cc;
        float s = 0.0f;
        #pragma unroll
        for (int d = 0; d < Dd; d++) s += s_sum[bb * 8 + d] * dcn[c * 8 + d];
        out[idx] = s * (1.0f / (float)Ntot);
    }
}

extern "C" void kernel_launch(void* const* d_in, const int* in_sizes, int n_in,
                              void* d_out, int out_size)
{
    const float* xin = (const float*)d_in[0];  // inputs [128,12,12,32,8]
    const float* Wg  = (const float*)d_in[1];  // W [4608,8,32]
    const float* dcg = (const float*)d_in[2];  // digit_caps [10,8]
    float* out = (float*)d_out;

    size_t smemBytes = (size_t)(JB * WSTR + BB * XSTR + NSEG * 256) * sizeof(float);
    cudaFuncSetAttribute(caps_main_kernel,
                         cudaFuncAttributeMaxDynamicSharedMemorySize,
                         (int)smemBytes);
    dim3 grid(Jtot / JB, Bsz / BB);
    caps_main_kernel<<<grid, NTHR, smemBytes>>>(xin, Wg, dcg, out);
}